// round 13
// baseline (speedup 1.0000x reference)
#include <cuda_runtime.h>
#include <cuda_fp16.h>
#include <cstdint>

// ---------------------------------------------------------------------------
// B=8, L=2048, D=768.  All-fp16 cp.async GEMMs, ldmatrix fragments, 2 CTAs/SM.
// Precision tiers:
//   proj/sim : hi*hi in fp32-acc MMA; (hi*lo + lo*hi) corrections in fp16-acc
//              MMA (2x rate), promoted to fp32 once in epilogue
//   av/al    : 1xFP16 fp32-acc
//   out      : 1xFP16 fp32-acc
// ---------------------------------------------------------------------------
#define BATCH 8
#define SEQ   2048
#define DIM   768
#define TOK   (BATCH * SEQ)          // 16384

// Scratch (device globals: allocation-free rule)
__device__ __half g_vfh [TOK * DIM];                 // Vf hi   [16384,768]
__device__ __half g_vfl [TOK * DIM];
__device__ __half g_lfh [TOK * DIM];
__device__ __half g_lfl [TOK * DIM];
__device__ __half g_wvh [DIM * DIM];
__device__ __half g_wvl [DIM * DIM];
__device__ __half g_wlh [DIM * DIM];
__device__ __half g_wll [DIM * DIM];
__device__ __half g_vph [TOK * DIM];                 // vp hi
__device__ __half g_vpl [TOK * DIM];
__device__ __half g_lph [TOK * DIM];
__device__ __half g_lpl [TOK * DIM];
__device__ __half g_vpt [TOK * DIM];                 // vp^T [8][768][2048]
__device__ __half g_lpt [TOK * DIM];
__device__ float  g_sim [(long)BATCH * SEQ * SEQ];   // [8,2048,2048]
__device__ __half g_at  [(long)BATCH * SEQ * SEQ];   // attn
__device__ __half g_att [(long)BATCH * SEQ * SEQ];   // attn^T
__device__ __half g_cb  [(long)TOK * 2 * DIM];       // comb fp16 [16384,1536]
__device__ __half g_wo16[DIM * 2 * DIM];             // Wo fp16

// ---------------------------------------------------------------------------
// helpers
// ---------------------------------------------------------------------------
__device__ __forceinline__ uint32_t smem_u32(const void* p) {
    uint32_t a;
    asm("{ .reg .u64 t; cvta.to.shared.u64 t, %1; cvt.u32.u64 %0, t; }"
        : "=r"(a) : "l"(p));
    return a;
}
__device__ __forceinline__ void cp16(uint32_t s, const void* g) {
    asm volatile("cp.async.ca.shared.global [%0], [%1], 16;" :: "r"(s), "l"(g));
}
#define CP_COMMIT() asm volatile("cp.async.commit_group;" ::: "memory")
template<int N>
__device__ __forceinline__ void cp_wait() {
    asm volatile("cp.async.wait_group %0;" :: "n"(N) : "memory");
}
// fp32-accumulate MMA
__device__ __forceinline__ void mma16(float* d, const uint32_t* a, const uint32_t* b) {
    asm volatile(
        "mma.sync.aligned.m16n8k16.row.col.f32.f16.f16.f32 "
        "{%0,%1,%2,%3}, {%4,%5,%6,%7}, {%8,%9}, {%0,%1,%2,%3};"
        : "+f"(d[0]), "+f"(d[1]), "+f"(d[2]), "+f"(d[3])
        : "r"(a[0]), "r"(a[1]), "r"(a[2]), "r"(a[3]), "r"(b[0]), "r"(b[1]));
}
// fp16-accumulate MMA (2x rate path) — used for small correction terms only
__device__ __forceinline__ void mma16h(uint32_t* d, const uint32_t* a, const uint32_t* b) {
    asm volatile(
        "mma.sync.aligned.m16n8k16.row.col.f16.f16.f16.f16 "
        "{%0,%1}, {%2,%3,%4,%5}, {%6,%7}, {%0,%1};"
        : "+r"(d[0]), "+r"(d[1])
        : "r"(a[0]), "r"(a[1]), "r"(a[2]), "r"(a[3]), "r"(b[0]), "r"(b[1]));
}
#define LDM4(r, addr)                                                        \
    asm volatile("ldmatrix.sync.aligned.m8n8.x4.shared.b16 "                 \
                 "{%0,%1,%2,%3}, [%4];"                                      \
                 : "=r"((r)[0]), "=r"((r)[1]), "=r"((r)[2]), "=r"((r)[3])    \
                 : "r"(addr))
__device__ __forceinline__ void split_h(float a, __half& h, __half& l) {
    h = __float2half_rn(a);
    l = __float2half_rn(a - __half2float(h));
}

// SMEM tile: 128 rows x 32 k halves, row stride 40 halves (80 B, 16B-aligned)
#define ROWH    40
#define TILE16  (128 * ROWH)          // halves per tile (10240 B)

// fp16 cp.async stage loader: 128 rows x 32 k from src[(row0+r)*ld + k0 + c]
__device__ __forceinline__ void load_stage16(__half* dst, const __half* __restrict__ src,
                                             int ld, long row0, int k0, int tid)
{
#pragma unroll
    for (int p = 0; p < 2; ++p) {
        const int idx = tid + p * 256;       // 0..511
        const int r   = idx >> 2;            // 0..127
        const int c8  = (idx & 3) * 8;       // 0,8,16,24
        cp16(smem_u32(&dst[r * ROWH + c8]), &src[(row0 + r) * (long)ld + k0 + c8]);
    }
}

// ---------------------------------------------------------------------------
// All-fp16 GEMM body: mma.sync m16n8k16 + ldmatrix fragments,
// CTA tile 128x128, K-chunk 32, NST-stage cp.async pipeline.
//   C[m,n] = sum_k opA[m,k]*opB[n,k]
//   SA/SB: operand has hi+lo tiles (corrections go through fp16-acc MMAs).
//   WMODE: 0 = fp32 out, 1 = fp16 out, 2 = fp16 hi/lo split out
// ---------------------------------------------------------------------------
template<bool SA, bool SB, int NST, int WMODE, bool BIAS>
__device__ __forceinline__ void gemm16_body(
    const __half* __restrict__ Ah, const __half* __restrict__ Al, int lda,
    const __half* __restrict__ Bh, const __half* __restrict__ Bl, int ldb,
    float* __restrict__ Cf, __half* __restrict__ Ch, __half* __restrict__ Cl, int ldc,
    int K, const float* __restrict__ bias, __half* hsm)
{
    constexpr int NTIL = (SA ? 2 : 1) + (SB ? 2 : 1);
    constexpr int STG  = NTIL * TILE16;
    constexpr bool CORR = (SA || SB);

    const int tid  = threadIdx.x;
    const int lane = tid & 31;
    const int wid  = tid >> 5;
    const int wm   = wid & 3;
    const int wn   = wid >> 2;
    const long m0  = (long)blockIdx.y * 128;
    const long n0  = (long)blockIdx.x * 128;
    const int lr   = lane >> 2;
    const int lc   = lane & 3;

    // ldmatrix per-lane offset (halves): row = (lane&15), col-group = (lane>>4)*8
    const uint32_t sb32 = smem_u32(hsm);
    const int loff  = (lane & 15) * ROWH + (lane >> 4) * 8;
    const int aoff0 = (wm * 32) * ROWH + loff;
    const int boff0 = (wn * 64) * ROWH + loff;

    float acc[2][8][4];
    uint32_t corr[2][8][2];
#pragma unroll
    for (int i = 0; i < 2; ++i)
#pragma unroll
        for (int j = 0; j < 8; ++j) {
#pragma unroll
            for (int q = 0; q < 4; ++q) acc[i][j][q] = 0.f;
            if (CORR) { corr[i][j][0] = 0u; corr[i][j][1] = 0u; }
        }

    const int NIT = K / 32;

    auto issue = [&](int st) {
        if (st < NIT) {
            __half* s = hsm + (st % NST) * STG;
            const int k0 = st * 32;
            load_stage16(s, Ah, lda, m0, k0, tid);
            if (SA) load_stage16(s + TILE16, Al, lda, m0, k0, tid);
            __half* sb = s + (SA ? 2 : 1) * TILE16;
            load_stage16(sb, Bh, ldb, n0, k0, tid);
            if (SB) load_stage16(sb + TILE16, Bl, ldb, n0, k0, tid);
        }
        CP_COMMIT();
    };

#pragma unroll
    for (int s = 0; s < NST - 1; ++s) issue(s);

    for (int it = 0; it < NIT; ++it) {
        cp_wait<NST - 2>();
        __syncthreads();
        issue(it + NST - 1);

        const int stA  = (it % NST) * STG;          // halves
        const int stAl = stA + TILE16;
        const int stB  = stA + (SA ? 2 : 1) * TILE16;
        const int stBl = stB + TILE16;

#pragma unroll
        for (int ks = 0; ks < 2; ++ks) {
            const int kb = ks * 16;
            uint32_t ah[2][4], al[2][4];
#pragma unroll
            for (int mt = 0; mt < 2; ++mt) {
                const int ao = aoff0 + mt * 16 * ROWH + kb;
                LDM4(ah[mt], sb32 + (uint32_t)(stA + ao) * 2);
                if (SA) LDM4(al[mt], sb32 + (uint32_t)(stAl + ao) * 2);
            }
#pragma unroll
            for (int ntg = 0; ntg < 4; ++ntg) {
                const int bo = boff0 + ntg * 16 * ROWH + kb;
                uint32_t bh4[4], bl4[4];
                LDM4(bh4, sb32 + (uint32_t)(stB + bo) * 2);
                if (SB) LDM4(bl4, sb32 + (uint32_t)(stBl + bo) * 2);
#pragma unroll
                for (int sub = 0; sub < 2; ++sub) {
                    const int nt = ntg * 2 + sub;
                    uint32_t bbh[2] = {bh4[sub], bh4[2 + sub]};
                    uint32_t bbl[2];
                    if (SB) { bbl[0] = bl4[sub]; bbl[1] = bl4[2 + sub]; }
#pragma unroll
                    for (int mt = 0; mt < 2; ++mt) {
                        mma16(acc[mt][nt], ah[mt], bbh);         // hi*hi  (fp32 acc)
                        if (SB) mma16h(corr[mt][nt], ah[mt], bbl); // hi*lo (fp16 acc)
                        if (SA) mma16h(corr[mt][nt], al[mt], bbh); // lo*hi (fp16 acc)
                    }
                }
            }
        }
    }

    // ---- epilogue ----
#pragma unroll
    for (int mt = 0; mt < 2; ++mt) {
        const long r0 = m0 + wm * 32 + mt * 16 + lr;
#pragma unroll
        for (int nt = 0; nt < 8; ++nt) {
            const long c = n0 + wn * 64 + nt * 8 + lc * 2;
            float v[4] = {acc[mt][nt][0], acc[mt][nt][1], acc[mt][nt][2], acc[mt][nt][3]};
            if (CORR) {
                float2 c0 = __half22float2(*reinterpret_cast<__half2*>(&corr[mt][nt][0]));
                float2 c1 = __half22float2(*reinterpret_cast<__half2*>(&corr[mt][nt][1]));
                v[0] += c0.x; v[1] += c0.y; v[2] += c1.x; v[3] += c1.y;
            }
            if (BIAS) {
                float2 bb = *reinterpret_cast<const float2*>(&bias[c]);
                v[0] += bb.x; v[1] += bb.y; v[2] += bb.x; v[3] += bb.y;
            }
            if (WMODE == 0) {
                *reinterpret_cast<float2*>(&Cf[r0 * ldc + c])       = make_float2(v[0], v[1]);
                *reinterpret_cast<float2*>(&Cf[(r0 + 8) * ldc + c]) = make_float2(v[2], v[3]);
            } else if (WMODE == 1) {
                *reinterpret_cast<__half2*>(&Ch[r0 * ldc + c])       = __floats2half2_rn(v[0], v[1]);
                *reinterpret_cast<__half2*>(&Ch[(r0 + 8) * ldc + c]) = __floats2half2_rn(v[2], v[3]);
            } else {
                __half h[4], l[4];
#pragma unroll
                for (int q = 0; q < 4; ++q) split_h(v[q], h[q], l[q]);
                *reinterpret_cast<__half2*>(&Ch[r0 * ldc + c])       = __halves2half2(h[0], h[1]);
                *reinterpret_cast<__half2*>(&Ch[(r0 + 8) * ldc + c]) = __halves2half2(h[2], h[3]);
                *reinterpret_cast<__half2*>(&Cl[r0 * ldc + c])       = __halves2half2(l[0], l[1]);
                *reinterpret_cast<__half2*>(&Cl[(r0 + 8) * ldc + c]) = __halves2half2(l[2], l[3]);
            }
        }
    }
}

// ---------------------------------------------------------------------------
// GEMM kernel wrappers (all 2 CTAs/SM)
// ---------------------------------------------------------------------------
__global__ __launch_bounds__(256, 2)
void proj_gemm(const __half* __restrict__ vfh, const __half* __restrict__ vfl,
               const __half* __restrict__ lfh, const __half* __restrict__ lfl,
               const __half* __restrict__ wvh, const __half* __restrict__ wvl,
               const __half* __restrict__ wlh, const __half* __restrict__ wll,
               const float* __restrict__ bv, const float* __restrict__ bl,
               __half* __restrict__ vph, __half* __restrict__ vpl,
               __half* __restrict__ lph, __half* __restrict__ lpl)
{
    extern __shared__ __half hsm[];
    const int z = blockIdx.z;
    gemm16_body<true, true, 2, 2, true>(
        z ? lfh : vfh, z ? lfl : vfl, DIM,
        z ? wlh : wvh, z ? wll : wvl, DIM,
        nullptr, z ? lph : vph, z ? lpl : vpl, DIM,
        DIM, z ? bl : bv, hsm);
}

__global__ __launch_bounds__(256, 2)
void sim_gemm(const __half* __restrict__ vph, const __half* __restrict__ vpl,
              const __half* __restrict__ lph, const __half* __restrict__ lpl,
              float* __restrict__ sim)
{
    extern __shared__ __half hsm[];
    const long b  = blockIdx.z;
    const long sF = (long)SEQ * DIM;
    const long sS = (long)SEQ * SEQ;
    gemm16_body<true, true, 2, 0, false>(
        vph + b * sF, vpl + b * sF, DIM,
        lph + b * sF, lpl + b * sF, DIM,
        sim + b * sS, nullptr, nullptr, SEQ, DIM, nullptr, hsm);
}

__global__ __launch_bounds__(256, 2)
void avl_gemm(const __half* __restrict__ at,  const __half* __restrict__ att,
              const __half* __restrict__ vpt, const __half* __restrict__ lpt,
              __half* __restrict__ cb)
{
    extern __shared__ __half hsm[];
    const int z   = blockIdx.z;
    const long b  = z & 7;
    const long sS = (long)SEQ * SEQ;
    const long sF = (long)SEQ * DIM;
    const long sO = (long)SEQ * 2 * DIM;
    const __half* A = (z >> 3) ? (att + b * sS) : (at + b * sS);
    const __half* B = (z >> 3) ? (lpt + b * sF) : (vpt + b * sF);
    const long    co = b * sO + ((z >> 3) ? DIM : 0);
    gemm16_body<false, false, 4, 1, false>(
        A, nullptr, SEQ, B, nullptr, SEQ,
        nullptr, cb + co, nullptr, 2 * DIM, SEQ, nullptr, hsm);
}

__global__ __launch_bounds__(256, 2)
void out_gemm(const __half* __restrict__ cb,
              const __half* __restrict__ wo, const float* __restrict__ bo,
              float* __restrict__ out)
{
    extern __shared__ __half hsm[];
    gemm16_body<false, false, 3, 0, true>(
        cb, nullptr, 2 * DIM, wo, nullptr, 2 * DIM,
        out, nullptr, nullptr, DIM, 2 * DIM, bo, hsm);
}

// ---------------------------------------------------------------------------
// fp32 -> fp16 hi/lo split (elementwise), float4 granularity
// ---------------------------------------------------------------------------
__global__ __launch_bounds__(256)
void convert_split(const float* __restrict__ src, __half* __restrict__ h,
                   __half* __restrict__ l)
{
    const long i = (long)blockIdx.x * 256 + threadIdx.x;
    float4 v = reinterpret_cast<const float4*>(src)[i];
    __half hh[4], ll[4];
    split_h(v.x, hh[0], ll[0]); split_h(v.y, hh[1], ll[1]);
    split_h(v.z, hh[2], ll[2]); split_h(v.w, hh[3], ll[3]);
    uint2 ho, lo;
    *reinterpret_cast<__half2*>(&ho.x) = __halves2half2(hh[0], hh[1]);
    *reinterpret_cast<__half2*>(&ho.y) = __halves2half2(hh[2], hh[3]);
    *reinterpret_cast<__half2*>(&lo.x) = __halves2half2(ll[0], ll[1]);
    *reinterpret_cast<__half2*>(&lo.y) = __halves2half2(ll[2], ll[3]);
    reinterpret_cast<uint2*>(h)[i] = ho;
    reinterpret_cast<uint2*>(l)[i] = lo;
}

__global__ __launch_bounds__(256)
void wo_convert(const float* __restrict__ Wo, __half* __restrict__ wo16)
{
    const int i = blockIdx.x * 256 + threadIdx.x;
    float2 v = *reinterpret_cast<const float2*>(&Wo[i * 2]);
    *reinterpret_cast<__half2*>(&wo16[i * 2]) = __floats2half2_rn(v.x, v.y);
}

// ---------------------------------------------------------------------------
// fp16 tiled transposes
// ---------------------------------------------------------------------------
__global__ __launch_bounds__(256)
void transpose16(const __half* __restrict__ src, __half* __restrict__ dst,
                 int R, int C, long stride)
{
    __shared__ __half t[32][34];
    const long b  = blockIdx.z;
    const int  x0 = blockIdx.x * 32;
    const int  y0 = blockIdx.y * 32;
    const __half* s = src + b * stride;
    __half*       d = dst + b * stride;
    const int tx = threadIdx.x, ty = threadIdx.y;
#pragma unroll
    for (int i = 0; i < 4; ++i)
        t[ty + i * 8][tx] = s[(long)(y0 + ty + i * 8) * C + x0 + tx];
    __syncthreads();
#pragma unroll
    for (int i = 0; i < 4; ++i)
        d[(long)(x0 + ty + i * 8) * R + y0 + tx] = t[tx][ty + i * 8];
}

__global__ __launch_bounds__(256)
void transpose_vl(const __half* __restrict__ vph, __half* __restrict__ vpt,
                  const __half* __restrict__ lph, __half* __restrict__ lpt)
{
    __shared__ __half t[32][34];
    const int z = blockIdx.z;
    const long b  = z & 7;
    const long stride = (long)SEQ * DIM;
    const __half* s = ((z >> 3) ? lph : vph) + b * stride;
    __half*       d = ((z >> 3) ? lpt : vpt) + b * stride;
    const int x0 = blockIdx.x * 32;
    const int y0 = blockIdx.y * 32;
    const int tx = threadIdx.x & 31, ty = threadIdx.x >> 5;
#pragma unroll
    for (int i = 0; i < 4; ++i)
        t[ty + i * 8][tx] = s[(long)(y0 + ty + i * 8) * DIM + x0 + tx];
    __syncthreads();
#pragma unroll
    for (int i = 0; i < 4; ++i)
        d[(long)(x0 + ty + i * 8) * SEQ + y0 + tx] = t[tx][ty + i * 8];
}

// ---------------------------------------------------------------------------
// Row softmax: sim fp32 -> attn fp16. One block per row of 2048.
// ---------------------------------------------------------------------------
__global__ __launch_bounds__(256)
void softmax2048h(const float* __restrict__ S, __half* __restrict__ O)
{
    const float* p = S + (long)blockIdx.x * 2048;
    __half*      o = O + (long)blockIdx.x * 2048;
    const int tid = threadIdx.x;

    float4 v0 = reinterpret_cast<const float4*>(p)[tid];
    float4 v1 = reinterpret_cast<const float4*>(p)[tid + 256];

    float mx = fmaxf(fmaxf(fmaxf(v0.x, v0.y), fmaxf(v0.z, v0.w)),
                     fmaxf(fmaxf(v1.x, v1.y), fmaxf(v1.z, v1.w)));

    __shared__ float red[8];
#pragma unroll
    for (int ofs = 16; ofs > 0; ofs >>= 1) mx = fmaxf(mx, __shfl_xor_sync(0xffffffffu, mx, ofs));
    if ((tid & 31) == 0) red[tid >> 5] = mx;
    __syncthreads();
    if (tid == 0) {
        float m = red[0];
#pragma unroll
        for (int w = 1; w < 8; ++w) m = fmaxf(m, red[w]);
        red[0] = m;
    }
    __syncthreads();
    mx = red[0];
    __syncthreads();

    v0.x = __expf(v0.x - mx); v0.y = __expf(v0.y - mx);
    v0.z = __expf(v0.z - mx); v0.w = __expf(v0.w - mx);
    v1.x = __expf(v1.x - mx); v1.y = __expf(v1.y - mx);
    v1.z = __expf(v1.z - mx); v1.w = __expf(v1.w - mx);

    float s = (v0.x + v0.y + v0.z + v0.w) + (v1.x + v1.y + v1.z + v1.w);
#pragma unroll
    for (int ofs = 16; ofs > 0; ofs >>= 1) s += __shfl_xor_sync(0xffffffffu, s, ofs);
    if ((tid & 31) == 0) red[tid >> 5] = s;
    __syncthreads();
    if (tid == 0) {
        float t = 0.f;
#pragma unroll
        for (int w = 0; w < 8; ++w) t += red[w];
        red[0] = t;
    }
    __syncthreads();
    const float inv = 1.0f / red[0];

    uint2 o0, o1;
    *reinterpret_cast<__half2*>(&o0.x) = __floats2half2_rn(v0.x * inv, v0.y * inv);
    *reinterpret_cast<__half2*>(&o0.y) = __floats2half2_rn(v0.z * inv, v0.w * inv);
    *reinterpret_cast<__half2*>(&o1.x) = __floats2half2_rn(v1.x * inv, v1.y * inv);
    *reinterpret_cast<__half2*>(&o1.y) = __floats2half2_rn(v1.z * inv, v1.w * inv);
    reinterpret_cast<uint2*>(o)[tid]       = o0;
    reinterpret_cast<uint2*>(o)[tid + 256] = o1;
}

// ---------------------------------------------------------------------------
// Launch
// ---------------------------------------------------------------------------
extern "C" void kernel_launch(void* const* d_in, const int* in_sizes, int n_in,
                              void* d_out, int out_size)
{
    const float* Vf = (const float*)d_in[0];
    const float* Lf = (const float*)d_in[1];
    const float* Wv = (const float*)d_in[2];
    const float* bv = (const float*)d_in[3];
    const float* Wl = (const float*)d_in[4];
    const float* bl = (const float*)d_in[5];
    const float* Wo = (const float*)d_in[6];
    const float* bo = (const float*)d_in[7];
    float* out = (float*)d_out;

    __half *vfh, *vfl, *lfh, *lfl, *wvh, *wvl, *wlh, *wll;
    __half *vph, *vpl, *lph, *lpl, *vpt, *lpt, *at, *att, *cb, *wo16;
    float* sim;
    cudaGetSymbolAddress((void**)&vfh, g_vfh);
    cudaGetSymbolAddress((void**)&vfl, g_vfl);
    cudaGetSymbolAddress((void**)&lfh, g_lfh);
    cudaGetSymbolAddress((void**)&lfl, g_lfl);
    cudaGetSymbolAddress((void**)&wvh, g_wvh);
    cudaGetSymbolAddress((void**)&wvl, g_wvl);
    cudaGetSymbolAddress((void**)&wlh, g_wlh);
    cudaGetSymbolAddress((void**)&wll, g_wll);
    cudaGetSymbolAddress((void**)&vph, g_vph);
    cudaGetSymbolAddress((void**)&vpl, g_vpl);
    cudaGetSymbolAddress((void**)&lph, g_lph);
    cudaGetSymbolAddress((void**)&lpl, g_lpl);
    cudaGetSymbolAddress((void**)&vpt, g_vpt);
    cudaGetSymbolAddress((void**)&lpt, g_lpt);
    cudaGetSymbolAddress((void**)&sim, g_sim);
    cudaGetSymbolAddress((void**)&at,  g_at);
    cudaGetSymbolAddress((void**)&att, g_att);
    cudaGetSymbolAddress((void**)&cb,  g_cb);
    cudaGetSymbolAddress((void**)&wo16, g_wo16);

    const int S2 = 4 * TILE16 * 2 * 2;   // 81920 (proj, sim)
    const int S4 = 2 * TILE16 * 4 * 2;   // 81920 (avl)
    const int S3 = 2 * TILE16 * 3 * 2;   // 61440 (out)
    cudaFuncSetAttribute(proj_gemm, cudaFuncAttributeMaxDynamicSharedMemorySize, S2);
    cudaFuncSetAttribute(sim_gemm,  cudaFuncAttributeMaxDynamicSharedMemorySize, S2);
    cudaFuncSetAttribute(avl_gemm,  cudaFuncAttributeMaxDynamicSharedMemorySize, S4);
    cudaFuncSetAttribute(out_gemm,  cudaFuncAttributeMaxDynamicSharedMemorySize, S3);

    const dim3 blk(256);
    const long sS = (long)SEQ * SEQ;

    // input conversions
    wo_convert<<<DIM * 2 * DIM / 512, blk>>>(Wo, wo16);
    convert_split<<<TOK * DIM / 1024, blk>>>(Vf, vfh, vfl);
    convert_split<<<TOK * DIM / 1024, blk>>>(Lf, lfh, lfl);
    convert_split<<<DIM * DIM / 1024, blk>>>(Wv, wvh, wvl);
    convert_split<<<DIM * DIM / 1024, blk>>>(Wl, wlh, wll);
    // projections (3x, corrections in f16-acc) -> vp/lp hi+lo fp16
    proj_gemm<<<dim3(DIM/128, TOK/128, 2), blk, S2>>>(
        vfh, vfl, lfh, lfl, wvh, wvl, wlh, wll, bv, bl, vph, vpl, lph, lpl);
    // vp^T and lp^T, one launch
    transpose_vl<<<dim3(DIM/32, SEQ/32, 2 * BATCH), blk>>>(vph, vpt, lph, lpt);
    // sim (3x, corrections in f16-acc)
    sim_gemm<<<dim3(SEQ/128, SEQ/128, BATCH), blk, S2>>>(vph, vpl, lph, lpl, sim);
    // softmax -> attn fp16
    softmax2048h<<<TOK, blk>>>(sim, at);
    // attn^T fp16
    transpose16<<<dim3(SEQ/32, SEQ/32, BATCH), dim3(32, 8)>>>(at, att, SEQ, SEQ, sS);
    // av + al (1x) -> comb fp16
    avl_gemm<<<dim3(DIM/128, SEQ/128, 2 * BATCH), blk, S4>>>(at, att, vpt, lpt, cb);
    // out (1x)
    out_gemm<<<dim3(DIM/128, TOK/128, 1), blk, S3>>>(cb, wo16, bo, out);
}

// round 14
// speedup vs baseline: 1.1209x; 1.1209x over previous
#include <cuda_runtime.h>
#include <cuda_fp16.h>
#include <cstdint>

// ---------------------------------------------------------------------------
// B=8, L=2048, D=768.  All-fp16 cp.async GEMMs, ldmatrix fragments, 2 CTAs/SM.
//   proj : 3xFP16 (inputs pre-split to fp16 hi/lo), writes vp/lp hi+lo
//   sim  : 3xFP16
//   av/al: 1xFP16, transposed operands loaded in-kernel via ldmatrix.trans
//   out  : 1xFP16
// ---------------------------------------------------------------------------
#define BATCH 8
#define SEQ   2048
#define DIM   768
#define TOK   (BATCH * SEQ)          // 16384

// Scratch (device globals: allocation-free rule)
__device__ __half g_vfh [TOK * DIM];                 // Vf hi   [16384,768]
__device__ __half g_vfl [TOK * DIM];
__device__ __half g_lfh [TOK * DIM];
__device__ __half g_lfl [TOK * DIM];
__device__ __half g_wvh [DIM * DIM];
__device__ __half g_wvl [DIM * DIM];
__device__ __half g_wlh [DIM * DIM];
__device__ __half g_wll [DIM * DIM];
__device__ __half g_vph [TOK * DIM];                 // vp hi
__device__ __half g_vpl [TOK * DIM];
__device__ __half g_lph [TOK * DIM];
__device__ __half g_lpl [TOK * DIM];
__device__ float  g_sim [(long)BATCH * SEQ * SEQ];   // [8,2048,2048]
__device__ __half g_at  [(long)BATCH * SEQ * SEQ];   // attn fp16
__device__ __half g_cb  [(long)TOK * 2 * DIM];       // comb fp16 [16384,1536]
__device__ __half g_wo16[DIM * 2 * DIM];             // Wo fp16

// ---------------------------------------------------------------------------
// helpers
// ---------------------------------------------------------------------------
__device__ __forceinline__ uint32_t smem_u32(const void* p) {
    uint32_t a;
    asm("{ .reg .u64 t; cvta.to.shared.u64 t, %1; cvt.u32.u64 %0, t; }"
        : "=r"(a) : "l"(p));
    return a;
}
__device__ __forceinline__ void cp16(uint32_t s, const void* g) {
    asm volatile("cp.async.ca.shared.global [%0], [%1], 16;" :: "r"(s), "l"(g));
}
#define CP_COMMIT() asm volatile("cp.async.commit_group;" ::: "memory")
template<int N>
__device__ __forceinline__ void cp_wait() {
    asm volatile("cp.async.wait_group %0;" :: "n"(N) : "memory");
}
__device__ __forceinline__ void mma16(float* d, const uint32_t* a, const uint32_t* b) {
    asm volatile(
        "mma.sync.aligned.m16n8k16.row.col.f32.f16.f16.f32 "
        "{%0,%1,%2,%3}, {%4,%5,%6,%7}, {%8,%9}, {%0,%1,%2,%3};"
        : "+f"(d[0]), "+f"(d[1]), "+f"(d[2]), "+f"(d[3])
        : "r"(a[0]), "r"(a[1]), "r"(a[2]), "r"(a[3]), "r"(b[0]), "r"(b[1]));
}
#define LDM4(r, addr)                                                        \
    asm volatile("ldmatrix.sync.aligned.m8n8.x4.shared.b16 "                 \
                 "{%0,%1,%2,%3}, [%4];"                                      \
                 : "=r"((r)[0]), "=r"((r)[1]), "=r"((r)[2]), "=r"((r)[3])    \
                 : "r"(addr))
#define LDM4T(r, addr)                                                       \
    asm volatile("ldmatrix.sync.aligned.m8n8.x4.trans.shared.b16 "           \
                 "{%0,%1,%2,%3}, [%4];"                                      \
                 : "=r"((r)[0]), "=r"((r)[1]), "=r"((r)[2]), "=r"((r)[3])    \
                 : "r"(addr))
__device__ __forceinline__ void split_h(float a, __half& h, __half& l) {
    h = __float2half_rn(a);
    l = __float2half_rn(a - __half2float(h));
}

// Normal (row-major) SMEM tile: 128 rows x 32 k halves, stride 40 (80 B)
#define ROWH    40
#define TILE16  (128 * ROWH)          // 10240 B
// Transposed-load SMEM tile: 32 k-rows x 128 cols, stride 136 (272 B)
#define TROW    136
#define TTILE16 (32 * TROW)           // 8704 B

// normal stage loader: 128 rows x 32 k from src[(row0+r)*ld + k0 + c]
__device__ __forceinline__ void load_stage16(__half* dst, const __half* __restrict__ src,
                                             int ld, long row0, int k0, int tid)
{
#pragma unroll
    for (int p = 0; p < 2; ++p) {
        const int idx = tid + p * 256;       // 0..511
        const int r   = idx >> 2;            // 0..127
        const int c8  = (idx & 3) * 8;       // 0,8,16,24
        cp16(smem_u32(&dst[r * ROWH + c8]), &src[(row0 + r) * (long)ld + k0 + c8]);
    }
}
// trans stage loader: 32 k-rows x 128 cols from src[(k0+r)*ld + col0 + c]
__device__ __forceinline__ void load_trans16(__half* dst, const __half* __restrict__ src,
                                             int ld, long col0, int k0, int tid)
{
#pragma unroll
    for (int p = 0; p < 2; ++p) {
        const int idx = tid + p * 256;       // 0..511
        const int r   = idx >> 4;            // 0..31
        const int c8  = (idx & 15) * 8;      // 0..120
        cp16(smem_u32(&dst[r * TROW + c8]), &src[(long)(k0 + r) * ld + col0 + c8]);
    }
}

// ---------------------------------------------------------------------------
// Generic GEMM body (normal operands): mma.sync + ldmatrix, CTA 128x128,
// K-chunk 32, NST-stage cp.async pipeline.
//   SA/SB: hi+lo split operand.  WMODE: 0 fp32 out, 1 fp16 out, 2 fp16 hi/lo
// ---------------------------------------------------------------------------
template<bool SA, bool SB, int NST, int WMODE, bool BIAS>
__device__ __forceinline__ void gemm16_body(
    const __half* __restrict__ Ah, const __half* __restrict__ Al, int lda,
    const __half* __restrict__ Bh, const __half* __restrict__ Bl, int ldb,
    float* __restrict__ Cf, __half* __restrict__ Ch, __half* __restrict__ Cl, int ldc,
    int K, const float* __restrict__ bias, __half* hsm)
{
    constexpr int NTIL = (SA ? 2 : 1) + (SB ? 2 : 1);
    constexpr int STG  = NTIL * TILE16;

    const int tid  = threadIdx.x;
    const int lane = tid & 31;
    const int wid  = tid >> 5;
    const int wm   = wid & 3;
    const int wn   = wid >> 2;
    const long m0  = (long)blockIdx.y * 128;
    const long n0  = (long)blockIdx.x * 128;
    const int lr   = lane >> 2;
    const int lc   = lane & 3;

    const uint32_t sb32 = smem_u32(hsm);
    const int loff  = (lane & 15) * ROWH + (lane >> 4) * 8;
    const int aoff0 = (wm * 32) * ROWH + loff;
    const int boff0 = (wn * 64) * ROWH + loff;

    float acc[2][8][4];
#pragma unroll
    for (int i = 0; i < 2; ++i)
#pragma unroll
        for (int j = 0; j < 8; ++j)
#pragma unroll
            for (int q = 0; q < 4; ++q) acc[i][j][q] = 0.f;

    const int NIT = K / 32;

    auto issue = [&](int st) {
        if (st < NIT) {
            __half* s = hsm + (st % NST) * STG;
            const int k0 = st * 32;
            load_stage16(s, Ah, lda, m0, k0, tid);
            if (SA) load_stage16(s + TILE16, Al, lda, m0, k0, tid);
            __half* sb = s + (SA ? 2 : 1) * TILE16;
            load_stage16(sb, Bh, ldb, n0, k0, tid);
            if (SB) load_stage16(sb + TILE16, Bl, ldb, n0, k0, tid);
        }
        CP_COMMIT();
    };

#pragma unroll
    for (int s = 0; s < NST - 1; ++s) issue(s);

    for (int it = 0; it < NIT; ++it) {
        cp_wait<NST - 2>();
        __syncthreads();
        issue(it + NST - 1);

        const int stA  = (it % NST) * STG;
        const int stAl = stA + TILE16;
        const int stB  = stA + (SA ? 2 : 1) * TILE16;
        const int stBl = stB + TILE16;

#pragma unroll
        for (int ks = 0; ks < 2; ++ks) {
            const int kb = ks * 16;
            uint32_t ah[2][4], al[2][4];
#pragma unroll
            for (int mt = 0; mt < 2; ++mt) {
                const int ao = aoff0 + mt * 16 * ROWH + kb;
                LDM4(ah[mt], sb32 + (uint32_t)(stA + ao) * 2);
                if (SA) LDM4(al[mt], sb32 + (uint32_t)(stAl + ao) * 2);
            }
#pragma unroll
            for (int ntg = 0; ntg < 4; ++ntg) {
                const int bo = boff0 + ntg * 16 * ROWH + kb;
                uint32_t bh4[4], bl4[4];
                LDM4(bh4, sb32 + (uint32_t)(stB + bo) * 2);
                if (SB) LDM4(bl4, sb32 + (uint32_t)(stBl + bo) * 2);
#pragma unroll
                for (int sub = 0; sub < 2; ++sub) {
                    const int nt = ntg * 2 + sub;
                    uint32_t bh[2] = {bh4[sub], bh4[2 + sub]};
                    uint32_t bl[2];
                    if (SB) { bl[0] = bl4[sub]; bl[1] = bl4[2 + sub]; }
#pragma unroll
                    for (int mt = 0; mt < 2; ++mt) {
                        mma16(acc[mt][nt], ah[mt], bh);
                        if (SB) mma16(acc[mt][nt], ah[mt], bl);
                        if (SA) mma16(acc[mt][nt], al[mt], bh);
                    }
                }
            }
        }
    }

    // ---- epilogue ----
#pragma unroll
    for (int mt = 0; mt < 2; ++mt) {
        const long r0 = m0 + wm * 32 + mt * 16 + lr;
#pragma unroll
        for (int nt = 0; nt < 8; ++nt) {
            const long c = n0 + wn * 64 + nt * 8 + lc * 2;
            float v[4] = {acc[mt][nt][0], acc[mt][nt][1], acc[mt][nt][2], acc[mt][nt][3]};
            if (BIAS) {
                float2 bb = *reinterpret_cast<const float2*>(&bias[c]);
                v[0] += bb.x; v[1] += bb.y; v[2] += bb.x; v[3] += bb.y;
            }
            if (WMODE == 0) {
                *reinterpret_cast<float2*>(&Cf[r0 * ldc + c])       = make_float2(v[0], v[1]);
                *reinterpret_cast<float2*>(&Cf[(r0 + 8) * ldc + c]) = make_float2(v[2], v[3]);
            } else if (WMODE == 1) {
                *reinterpret_cast<__half2*>(&Ch[r0 * ldc + c])       = __floats2half2_rn(v[0], v[1]);
                *reinterpret_cast<__half2*>(&Ch[(r0 + 8) * ldc + c]) = __floats2half2_rn(v[2], v[3]);
            } else {
                __half h[4], l[4];
#pragma unroll
                for (int q = 0; q < 4; ++q) split_h(v[q], h[q], l[q]);
                *reinterpret_cast<__half2*>(&Ch[r0 * ldc + c])       = __halves2half2(h[0], h[1]);
                *reinterpret_cast<__half2*>(&Ch[(r0 + 8) * ldc + c]) = __halves2half2(h[2], h[3]);
                *reinterpret_cast<__half2*>(&Cl[r0 * ldc + c])       = __halves2half2(l[0], l[1]);
                *reinterpret_cast<__half2*>(&Cl[(r0 + 8) * ldc + c]) = __halves2half2(l[2], l[3]);
            }
        }
    }
}

// ---------------------------------------------------------------------------
// av/al GEMM body: B always transposed-load; A normal (TRA=0) or trans (TRA=1).
// 1xFP16, fp16 out.  C[m,n] = sum_k opA[m,k]*opB[n,k]
//   TRA=0: opA[m,k] = A[m*lda+k]   (attn @ vp)
//   TRA=1: opA[m,k] = A[k*lda+m]   (attn^T @ lp)
//   opB[n,k] = B[k*ldb+n] always (vp/lp are [k][n])
// ---------------------------------------------------------------------------
template<bool TRA>
__device__ __forceinline__ void gemm_avl(
    const __half* __restrict__ A, int lda,
    const __half* __restrict__ B, int ldb,
    __half* __restrict__ Ch, int ldc, int K, __half* hsm)
{
    constexpr int AT_H = TRA ? TTILE16 : TILE16;
    constexpr int STG  = AT_H + TTILE16;
    constexpr int NST  = 4;

    const int tid  = threadIdx.x;
    const int lane = tid & 31;
    const int wid  = tid >> 5;
    const int wm   = wid & 3;
    const int wn   = wid >> 2;
    const long m0  = (long)blockIdx.y * 128;
    const long n0  = (long)blockIdx.x * 128;
    const int lr   = lane >> 2;
    const int lc   = lane & 3;

    const uint32_t sb32 = smem_u32(hsm);
    const int loff   = (lane & 15) * ROWH + (lane >> 4) * 8;      // normal A
    const int rowsel = (lane & 7) + ((lane >> 4) << 3);           // trans tiles
    const int tcol   = lane & 8;

    float acc[2][8][4];
#pragma unroll
    for (int i = 0; i < 2; ++i)
#pragma unroll
        for (int j = 0; j < 8; ++j)
#pragma unroll
            for (int q = 0; q < 4; ++q) acc[i][j][q] = 0.f;

    const int NIT = K / 32;

    auto issue = [&](int st) {
        if (st < NIT) {
            __half* s = hsm + (st % NST) * STG;
            const int k0 = st * 32;
            if (!TRA) load_stage16(s, A, lda, m0, k0, tid);
            else      load_trans16(s, A, lda, m0, k0, tid);
            load_trans16(s + AT_H, B, ldb, n0, k0, tid);
        }
        CP_COMMIT();
    };

#pragma unroll
    for (int s = 0; s < NST - 1; ++s) issue(s);

    for (int it = 0; it < NIT; ++it) {
        cp_wait<NST - 2>();
        __syncthreads();
        issue(it + NST - 1);

        const int stA = (it % NST) * STG;
        const int stB = stA + AT_H;

#pragma unroll
        for (int ks = 0; ks < 2; ++ks) {
            const int kb = ks * 16;
            uint32_t ah[2][4];
#pragma unroll
            for (int mt = 0; mt < 2; ++mt) {
                if (!TRA) {
                    const int ao = (wm * 32 + mt * 16) * ROWH + loff + kb;
                    LDM4(ah[mt], sb32 + (uint32_t)(stA + ao) * 2);
                } else {
                    const int ao = (kb + rowsel) * TROW + wm * 32 + mt * 16 + tcol;
                    LDM4T(ah[mt], sb32 + (uint32_t)(stA + ao) * 2);
                }
            }
#pragma unroll
            for (int ntg = 0; ntg < 4; ++ntg) {
                const int bo = (kb + rowsel) * TROW + wn * 64 + ntg * 16 + tcol;
                uint32_t b4[4];
                LDM4T(b4, sb32 + (uint32_t)(stB + bo) * 2);
#pragma unroll
                for (int sub = 0; sub < 2; ++sub) {
                    uint32_t bb[2] = {b4[sub], b4[2 + sub]};
#pragma unroll
                    for (int mt = 0; mt < 2; ++mt)
                        mma16(acc[mt][ntg * 2 + sub], ah[mt], bb);
                }
            }
        }
    }

    // ---- epilogue (fp16 out) ----
#pragma unroll
    for (int mt = 0; mt < 2; ++mt) {
        const long r0 = m0 + wm * 32 + mt * 16 + lr;
#pragma unroll
        for (int nt = 0; nt < 8; ++nt) {
            const long c = n0 + wn * 64 + nt * 8 + lc * 2;
            *reinterpret_cast<__half2*>(&Ch[r0 * ldc + c]) =
                __floats2half2_rn(acc[mt][nt][0], acc[mt][nt][1]);
            *reinterpret_cast<__half2*>(&Ch[(r0 + 8) * ldc + c]) =
                __floats2half2_rn(acc[mt][nt][2], acc[mt][nt][3]);
        }
    }
}

// ---------------------------------------------------------------------------
// GEMM kernel wrappers (all 2 CTAs/SM)
// ---------------------------------------------------------------------------
__global__ __launch_bounds__(256, 2)
void proj_gemm(const __half* __restrict__ vfh, const __half* __restrict__ vfl,
               const __half* __restrict__ lfh, const __half* __restrict__ lfl,
               const __half* __restrict__ wvh, const __half* __restrict__ wvl,
               const __half* __restrict__ wlh, const __half* __restrict__ wll,
               const float* __restrict__ bv, const float* __restrict__ bl,
               __half* __restrict__ vph, __half* __restrict__ vpl,
               __half* __restrict__ lph, __half* __restrict__ lpl)
{
    extern __shared__ __half hsm[];
    const int z = blockIdx.z;
    gemm16_body<true, true, 2, 2, true>(
        z ? lfh : vfh, z ? lfl : vfl, DIM,
        z ? wlh : wvh, z ? wll : wvl, DIM,
        nullptr, z ? lph : vph, z ? lpl : vpl, DIM,
        DIM, z ? bl : bv, hsm);
}

__global__ __launch_bounds__(256, 2)
void sim_gemm(const __half* __restrict__ vph, const __half* __restrict__ vpl,
              const __half* __restrict__ lph, const __half* __restrict__ lpl,
              float* __restrict__ sim)
{
    extern __shared__ __half hsm[];
    const long b  = blockIdx.z;
    const long sF = (long)SEQ * DIM;
    const long sS = (long)SEQ * SEQ;
    gemm16_body<true, true, 2, 0, false>(
        vph + b * sF, vpl + b * sF, DIM,
        lph + b * sF, lpl + b * sF, DIM,
        sim + b * sS, nullptr, nullptr, SEQ, DIM, nullptr, hsm);
}

// av/al: z in [0,16): b = z&7, mode = z>>3. Transposed operands via ldmatrix.trans.
__global__ __launch_bounds__(256, 2)
void avl_gemm(const __half* __restrict__ at,
              const __half* __restrict__ vph, const __half* __restrict__ lph,
              __half* __restrict__ cb)
{
    extern __shared__ __half hsm[];
    const int z   = blockIdx.z;
    const long b  = z & 7;
    const long sS = (long)SEQ * SEQ;
    const long sF = (long)SEQ * DIM;
    const long sO = (long)SEQ * 2 * DIM;
    if ((z >> 3) == 0) {
        // av = attn @ vp : A normal (attn [q][j]), B trans (vp [j][d])
        gemm_avl<false>(at + b * sS, SEQ, vph + b * sF, DIM,
                        cb + b * sO, 2 * DIM, SEQ, hsm);
    } else {
        // al = attn^T @ lp : A trans (attn [i][j]), B trans (lp [i][d])
        gemm_avl<true>(at + b * sS, SEQ, lph + b * sF, DIM,
                       cb + b * sO + DIM, 2 * DIM, SEQ, hsm);
    }
}

__global__ __launch_bounds__(256, 2)
void out_gemm(const __half* __restrict__ cb,
              const __half* __restrict__ wo, const float* __restrict__ bo,
              float* __restrict__ out)
{
    extern __shared__ __half hsm[];
    gemm16_body<false, false, 3, 0, true>(
        cb, nullptr, 2 * DIM, wo, nullptr, 2 * DIM,
        out, nullptr, nullptr, DIM, 2 * DIM, bo, hsm);
}

// ---------------------------------------------------------------------------
// fp32 -> fp16 hi/lo split (elementwise), float4 granularity
// ---------------------------------------------------------------------------
__global__ __launch_bounds__(256)
void convert_split(const float* __restrict__ src, __half* __restrict__ h,
                   __half* __restrict__ l)
{
    const long i = (long)blockIdx.x * 256 + threadIdx.x;
    float4 v = reinterpret_cast<const float4*>(src)[i];
    __half hh[4], ll[4];
    split_h(v.x, hh[0], ll[0]); split_h(v.y, hh[1], ll[1]);
    split_h(v.z, hh[2], ll[2]); split_h(v.w, hh[3], ll[3]);
    uint2 ho, lo;
    *reinterpret_cast<__half2*>(&ho.x) = __halves2half2(hh[0], hh[1]);
    *reinterpret_cast<__half2*>(&ho.y) = __halves2half2(hh[2], hh[3]);
    *reinterpret_cast<__half2*>(&lo.x) = __halves2half2(ll[0], ll[1]);
    *reinterpret_cast<__half2*>(&lo.y) = __halves2half2(ll[2], ll[3]);
    reinterpret_cast<uint2*>(h)[i] = ho;
    reinterpret_cast<uint2*>(l)[i] = lo;
}

__global__ __launch_bounds__(256)
void wo_convert(const float* __restrict__ Wo, __half* __restrict__ wo16)
{
    const int i = blockIdx.x * 256 + threadIdx.x;
    float2 v = *reinterpret_cast<const float2*>(&Wo[i * 2]);
    *reinterpret_cast<__half2*>(&wo16[i * 2]) = __floats2half2_rn(v.x, v.y);
}

// ---------------------------------------------------------------------------
// Row softmax: sim fp32 -> attn fp16. One block per row of 2048.
// ---------------------------------------------------------------------------
__global__ __launch_bounds__(256)
void softmax2048h(const float* __restrict__ S, __half* __restrict__ O)
{
    const float* p = S + (long)blockIdx.x * 2048;
    __half*      o = O + (long)blockIdx.x * 2048;
    const int tid = threadIdx.x;

    float4 v0 = reinterpret_cast<const float4*>(p)[tid];
    float4 v1 = reinterpret_cast<const float4*>(p)[tid + 256];

    float mx = fmaxf(fmaxf(fmaxf(v0.x, v0.y), fmaxf(v0.z, v0.w)),
                     fmaxf(fmaxf(v1.x, v1.y), fmaxf(v1.z, v1.w)));

    __shared__ float red[8];
#pragma unroll
    for (int ofs = 16; ofs > 0; ofs >>= 1) mx = fmaxf(mx, __shfl_xor_sync(0xffffffffu, mx, ofs));
    if ((tid & 31) == 0) red[tid >> 5] = mx;
    __syncthreads();
    if (tid == 0) {
        float m = red[0];
#pragma unroll
        for (int w = 1; w < 8; ++w) m = fmaxf(m, red[w]);
        red[0] = m;
    }
    __syncthreads();
    mx = red[0];
    __syncthreads();

    v0.x = __expf(v0.x - mx); v0.y = __expf(v0.y - mx);
    v0.z = __expf(v0.z - mx); v0.w = __expf(v0.w - mx);
    v1.x = __expf(v1.x - mx); v1.y = __expf(v1.y - mx);
    v1.z = __expf(v1.z - mx); v1.w = __expf(v1.w - mx);

    float s = (v0.x + v0.y + v0.z + v0.w) + (v1.x + v1.y + v1.z + v1.w);
#pragma unroll
    for (int ofs = 16; ofs > 0; ofs >>= 1) s += __shfl_xor_sync(0xffffffffu, s, ofs);
    if ((tid & 31) == 0) red[tid >> 5] = s;
    __syncthreads();
    if (tid == 0) {
        float t = 0.f;
#pragma unroll
        for (int w = 0; w < 8; ++w) t += red[w];
        red[0] = t;
    }
    __syncthreads();
    const float inv = 1.0f / red[0];

    uint2 o0, o1;
    *reinterpret_cast<__half2*>(&o0.x) = __floats2half2_rn(v0.x * inv, v0.y * inv);
    *reinterpret_cast<__half2*>(&o0.y) = __floats2half2_rn(v0.z * inv, v0.w * inv);
    *reinterpret_cast<__half2*>(&o1.x) = __floats2half2_rn(v1.x * inv, v1.y * inv);
    *reinterpret_cast<__half2*>(&o1.y) = __floats2half2_rn(v1.z * inv, v1.w * inv);
    reinterpret_cast<uint2*>(o)[tid]       = o0;
    reinterpret_cast<uint2*>(o)[tid + 256] = o1;
}

// ---------------------------------------------------------------------------
// Launch
// ---------------------------------------------------------------------------
extern "C" void kernel_launch(void* const* d_in, const int* in_sizes, int n_in,
                              void* d_out, int out_size)
{
    const float* Vf = (const float*)d_in[0];
    const float* Lf = (const float*)d_in[1];
    const float* Wv = (const float*)d_in[2];
    const float* bv = (const float*)d_in[3];
    const float* Wl = (const float*)d_in[4];
    const float* bl = (const float*)d_in[5];
    const float* Wo = (const float*)d_in[6];
    const float* bo = (const float*)d_in[7];
    float* out = (float*)d_out;

    __half *vfh, *vfl, *lfh, *lfl, *wvh, *wvl, *wlh, *wll;
    __half *vph, *vpl, *lph, *lpl, *at, *cb, *wo16;
    float* sim;
    cudaGetSymbolAddress((void**)&vfh, g_vfh);
    cudaGetSymbolAddress((void**)&vfl, g_vfl);
    cudaGetSymbolAddress((void**)&lfh, g_lfh);
    cudaGetSymbolAddress((void**)&lfl, g_lfl);
    cudaGetSymbolAddress((void**)&wvh, g_wvh);
    cudaGetSymbolAddress((void**)&wvl, g_wvl);
    cudaGetSymbolAddress((void**)&wlh, g_wlh);
    cudaGetSymbolAddress((void**)&wll, g_wll);
    cudaGetSymbolAddress((void**)&vph, g_vph);
    cudaGetSymbolAddress((void**)&vpl, g_vpl);
    cudaGetSymbolAddress((void**)&lph, g_lph);
    cudaGetSymbolAddress((void**)&lpl, g_lpl);
    cudaGetSymbolAddress((void**)&sim, g_sim);
    cudaGetSymbolAddress((void**)&at,  g_at);
    cudaGetSymbolAddress((void**)&cb,  g_cb);
    cudaGetSymbolAddress((void**)&wo16, g_wo16);

    const int S2  = 4 * TILE16 * 2 * 2;                 // 81920 (proj, sim)
    const int SAV = 4 * (TILE16 + TTILE16) * 2;         // 75776 (avl, worst mode)
    const int S3  = 2 * TILE16 * 3 * 2;                 // 61440 (out)
    cudaFuncSetAttribute(proj_gemm, cudaFuncAttributeMaxDynamicSharedMemorySize, S2);
    cudaFuncSetAttribute(sim_gemm,  cudaFuncAttributeMaxDynamicSharedMemorySize, S2);
    cudaFuncSetAttribute(avl_gemm,  cudaFuncAttributeMaxDynamicSharedMemorySize, SAV);
    cudaFuncSetAttribute(out_gemm,  cudaFuncAttributeMaxDynamicSharedMemorySize, S3);

    const dim3 blk(256);

    // input conversions
    wo_convert<<<DIM * 2 * DIM / 512, blk>>>(Wo, wo16);
    convert_split<<<TOK * DIM / 1024, blk>>>(Vf, vfh, vfl);
    convert_split<<<TOK * DIM / 1024, blk>>>(Lf, lfh, lfl);
    convert_split<<<DIM * DIM / 1024, blk>>>(Wv, wvh, wvl);
    convert_split<<<DIM * DIM / 1024, blk>>>(Wl, wlh, wll);
    // projections (3x) -> vp/lp hi+lo fp16
    proj_gemm<<<dim3(DIM/128, TOK/128, 2), blk, S2>>>(
        vfh, vfl, lfh, lfl, wvh, wvl, wlh, wll, bv, bl, vph, vpl, lph, lpl);
    // sim (3x)
    sim_gemm<<<dim3(SEQ/128, SEQ/128, BATCH), blk, S2>>>(vph, vpl, lph, lpl, sim);
    // softmax -> attn fp16
    softmax2048h<<<TOK, blk>>>(sim, at);
    // av + al (1x) -> comb fp16, transposes folded into ldmatrix.trans
    avl_gemm<<<dim3(DIM/128, SEQ/128, 2 * BATCH), blk, SAV>>>(at, vph, lph, cb);
    // out (1x)
    out_gemm<<<dim3(DIM/128, TOK/128, 1), blk, S3>>>(cb, wo16, bo, out);
}

// round 15
// speedup vs baseline: 1.1320x; 1.0099x over previous
#include <cuda_runtime.h>
#include <cuda_fp16.h>
#include <cstdint>

// ---------------------------------------------------------------------------
// B=8, L=2048, D=768.  All-fp16 cp.async GEMMs, ldmatrix fragments, 2 CTAs/SM.
//   proj : 3xFP16 (inputs pre-split to fp16 hi/lo), writes vp/lp hi+lo
//   sim  : 3xFP16
//   av/al: 1xFP16, transposed operands loaded in-kernel via ldmatrix.trans
//   out  : 1xFP16
// All input conversions fused into one kernel; softmax uses streaming loads.
// ---------------------------------------------------------------------------
#define BATCH 8
#define SEQ   2048
#define DIM   768
#define TOK   (BATCH * SEQ)          // 16384

// Scratch (device globals: allocation-free rule)
__device__ __half g_vfh [TOK * DIM];                 // Vf hi   [16384,768]
__device__ __half g_vfl [TOK * DIM];
__device__ __half g_lfh [TOK * DIM];
__device__ __half g_lfl [TOK * DIM];
__device__ __half g_wvh [DIM * DIM];
__device__ __half g_wvl [DIM * DIM];
__device__ __half g_wlh [DIM * DIM];
__device__ __half g_wll [DIM * DIM];
__device__ __half g_vph [TOK * DIM];                 // vp hi
__device__ __half g_vpl [TOK * DIM];
__device__ __half g_lph [TOK * DIM];
__device__ __half g_lpl [TOK * DIM];
__device__ float  g_sim [(long)BATCH * SEQ * SEQ];   // [8,2048,2048]
__device__ __half g_at  [(long)BATCH * SEQ * SEQ];   // attn fp16
__device__ __half g_cb  [(long)TOK * 2 * DIM];       // comb fp16 [16384,1536]
__device__ __half g_wo16[DIM * 2 * DIM];             // Wo fp16

// ---------------------------------------------------------------------------
// helpers
// ---------------------------------------------------------------------------
__device__ __forceinline__ uint32_t smem_u32(const void* p) {
    uint32_t a;
    asm("{ .reg .u64 t; cvta.to.shared.u64 t, %1; cvt.u32.u64 %0, t; }"
        : "=r"(a) : "l"(p));
    return a;
}
__device__ __forceinline__ void cp16(uint32_t s, const void* g) {
    asm volatile("cp.async.ca.shared.global [%0], [%1], 16;" :: "r"(s), "l"(g));
}
#define CP_COMMIT() asm volatile("cp.async.commit_group;" ::: "memory")
template<int N>
__device__ __forceinline__ void cp_wait() {
    asm volatile("cp.async.wait_group %0;" :: "n"(N) : "memory");
}
__device__ __forceinline__ void mma16(float* d, const uint32_t* a, const uint32_t* b) {
    asm volatile(
        "mma.sync.aligned.m16n8k16.row.col.f32.f16.f16.f32 "
        "{%0,%1,%2,%3}, {%4,%5,%6,%7}, {%8,%9}, {%0,%1,%2,%3};"
        : "+f"(d[0]), "+f"(d[1]), "+f"(d[2]), "+f"(d[3])
        : "r"(a[0]), "r"(a[1]), "r"(a[2]), "r"(a[3]), "r"(b[0]), "r"(b[1]));
}
#define LDM4(r, addr)                                                        \
    asm volatile("ldmatrix.sync.aligned.m8n8.x4.shared.b16 "                 \
                 "{%0,%1,%2,%3}, [%4];"                                      \
                 : "=r"((r)[0]), "=r"((r)[1]), "=r"((r)[2]), "=r"((r)[3])    \
                 : "r"(addr))
#define LDM4T(r, addr)                                                       \
    asm volatile("ldmatrix.sync.aligned.m8n8.x4.trans.shared.b16 "           \
                 "{%0,%1,%2,%3}, [%4];"                                      \
                 : "=r"((r)[0]), "=r"((r)[1]), "=r"((r)[2]), "=r"((r)[3])    \
                 : "r"(addr))
__device__ __forceinline__ void split_h(float a, __half& h, __half& l) {
    h = __float2half_rn(a);
    l = __float2half_rn(a - __half2float(h));
}
__device__ __forceinline__ float4 ldcs4(const float4* p) {
    float4 v;
    asm volatile("ld.global.cs.v4.f32 {%0,%1,%2,%3}, [%4];"
                 : "=f"(v.x), "=f"(v.y), "=f"(v.z), "=f"(v.w) : "l"(p));
    return v;
}

// Normal (row-major) SMEM tile: 128 rows x 32 k halves, stride 40 (80 B)
#define ROWH    40
#define TILE16  (128 * ROWH)          // 10240 B
// Transposed-load SMEM tile: 32 k-rows x 128 cols, stride 136 (272 B)
#define TROW    136
#define TTILE16 (32 * TROW)           // 8704 B

// normal stage loader: 128 rows x 32 k from src[(row0+r)*ld + k0 + c]
__device__ __forceinline__ void load_stage16(__half* dst, const __half* __restrict__ src,
                                             int ld, long row0, int k0, int tid)
{
#pragma unroll
    for (int p = 0; p < 2; ++p) {
        const int idx = tid + p * 256;       // 0..511
        const int r   = idx >> 2;            // 0..127
        const int c8  = (idx & 3) * 8;       // 0,8,16,24
        cp16(smem_u32(&dst[r * ROWH + c8]), &src[(row0 + r) * (long)ld + k0 + c8]);
    }
}
// trans stage loader: 32 k-rows x 128 cols from src[(k0+r)*ld + col0 + c]
__device__ __forceinline__ void load_trans16(__half* dst, const __half* __restrict__ src,
                                             int ld, long col0, int k0, int tid)
{
#pragma unroll
    for (int p = 0; p < 2; ++p) {
        const int idx = tid + p * 256;       // 0..511
        const int r   = idx >> 4;            // 0..31
        const int c8  = (idx & 15) * 8;      // 0..120
        cp16(smem_u32(&dst[r * TROW + c8]), &src[(long)(k0 + r) * ld + col0 + c8]);
    }
}

// ---------------------------------------------------------------------------
// Generic GEMM body (normal operands): mma.sync + ldmatrix, CTA 128x128,
// K-chunk 32, NST-stage cp.async pipeline.
//   SA/SB: hi+lo split operand.  WMODE: 0 fp32 out, 1 fp16 out, 2 fp16 hi/lo
// ---------------------------------------------------------------------------
template<bool SA, bool SB, int NST, int WMODE, bool BIAS>
__device__ __forceinline__ void gemm16_body(
    const __half* __restrict__ Ah, const __half* __restrict__ Al, int lda,
    const __half* __restrict__ Bh, const __half* __restrict__ Bl, int ldb,
    float* __restrict__ Cf, __half* __restrict__ Ch, __half* __restrict__ Cl, int ldc,
    int K, const float* __restrict__ bias, __half* hsm)
{
    constexpr int NTIL = (SA ? 2 : 1) + (SB ? 2 : 1);
    constexpr int STG  = NTIL * TILE16;

    const int tid  = threadIdx.x;
    const int lane = tid & 31;
    const int wid  = tid >> 5;
    const int wm   = wid & 3;
    const int wn   = wid >> 2;
    const long m0  = (long)blockIdx.y * 128;
    const long n0  = (long)blockIdx.x * 128;
    const int lr   = lane >> 2;
    const int lc   = lane & 3;

    const uint32_t sb32 = smem_u32(hsm);
    const int loff  = (lane & 15) * ROWH + (lane >> 4) * 8;
    const int aoff0 = (wm * 32) * ROWH + loff;
    const int boff0 = (wn * 64) * ROWH + loff;

    float acc[2][8][4];
#pragma unroll
    for (int i = 0; i < 2; ++i)
#pragma unroll
        for (int j = 0; j < 8; ++j)
#pragma unroll
            for (int q = 0; q < 4; ++q) acc[i][j][q] = 0.f;

    const int NIT = K / 32;

    auto issue = [&](int st) {
        if (st < NIT) {
            __half* s = hsm + (st % NST) * STG;
            const int k0 = st * 32;
            load_stage16(s, Ah, lda, m0, k0, tid);
            if (SA) load_stage16(s + TILE16, Al, lda, m0, k0, tid);
            __half* sb = s + (SA ? 2 : 1) * TILE16;
            load_stage16(sb, Bh, ldb, n0, k0, tid);
            if (SB) load_stage16(sb + TILE16, Bl, ldb, n0, k0, tid);
        }
        CP_COMMIT();
    };

#pragma unroll
    for (int s = 0; s < NST - 1; ++s) issue(s);

    for (int it = 0; it < NIT; ++it) {
        cp_wait<NST - 2>();
        __syncthreads();
        issue(it + NST - 1);

        const int stA  = (it % NST) * STG;
        const int stAl = stA + TILE16;
        const int stB  = stA + (SA ? 2 : 1) * TILE16;
        const int stBl = stB + TILE16;

#pragma unroll
        for (int ks = 0; ks < 2; ++ks) {
            const int kb = ks * 16;
            uint32_t ah[2][4], al[2][4];
#pragma unroll
            for (int mt = 0; mt < 2; ++mt) {
                const int ao = aoff0 + mt * 16 * ROWH + kb;
                LDM4(ah[mt], sb32 + (uint32_t)(stA + ao) * 2);
                if (SA) LDM4(al[mt], sb32 + (uint32_t)(stAl + ao) * 2);
            }
#pragma unroll
            for (int ntg = 0; ntg < 4; ++ntg) {
                const int bo = boff0 + ntg * 16 * ROWH + kb;
                uint32_t bh4[4], bl4[4];
                LDM4(bh4, sb32 + (uint32_t)(stB + bo) * 2);
                if (SB) LDM4(bl4, sb32 + (uint32_t)(stBl + bo) * 2);
#pragma unroll
                for (int sub = 0; sub < 2; ++sub) {
                    const int nt = ntg * 2 + sub;
                    uint32_t bh[2] = {bh4[sub], bh4[2 + sub]};
                    uint32_t bl[2];
                    if (SB) { bl[0] = bl4[sub]; bl[1] = bl4[2 + sub]; }
#pragma unroll
                    for (int mt = 0; mt < 2; ++mt) {
                        mma16(acc[mt][nt], ah[mt], bh);
                        if (SB) mma16(acc[mt][nt], ah[mt], bl);
                        if (SA) mma16(acc[mt][nt], al[mt], bh);
                    }
                }
            }
        }
    }

    // ---- epilogue ----
#pragma unroll
    for (int mt = 0; mt < 2; ++mt) {
        const long r0 = m0 + wm * 32 + mt * 16 + lr;
#pragma unroll
        for (int nt = 0; nt < 8; ++nt) {
            const long c = n0 + wn * 64 + nt * 8 + lc * 2;
            float v[4] = {acc[mt][nt][0], acc[mt][nt][1], acc[mt][nt][2], acc[mt][nt][3]};
            if (BIAS) {
                float2 bb = *reinterpret_cast<const float2*>(&bias[c]);
                v[0] += bb.x; v[1] += bb.y; v[2] += bb.x; v[3] += bb.y;
            }
            if (WMODE == 0) {
                *reinterpret_cast<float2*>(&Cf[r0 * ldc + c])       = make_float2(v[0], v[1]);
                *reinterpret_cast<float2*>(&Cf[(r0 + 8) * ldc + c]) = make_float2(v[2], v[3]);
            } else if (WMODE == 1) {
                *reinterpret_cast<__half2*>(&Ch[r0 * ldc + c])       = __floats2half2_rn(v[0], v[1]);
                *reinterpret_cast<__half2*>(&Ch[(r0 + 8) * ldc + c]) = __floats2half2_rn(v[2], v[3]);
            } else {
                __half h[4], l[4];
#pragma unroll
                for (int q = 0; q < 4; ++q) split_h(v[q], h[q], l[q]);
                *reinterpret_cast<__half2*>(&Ch[r0 * ldc + c])       = __halves2half2(h[0], h[1]);
                *reinterpret_cast<__half2*>(&Ch[(r0 + 8) * ldc + c]) = __halves2half2(h[2], h[3]);
                *reinterpret_cast<__half2*>(&Cl[r0 * ldc + c])       = __halves2half2(l[0], l[1]);
                *reinterpret_cast<__half2*>(&Cl[(r0 + 8) * ldc + c]) = __halves2half2(l[2], l[3]);
            }
        }
    }
}

// ---------------------------------------------------------------------------
// av/al GEMM body: B always transposed-load; A normal (TRA=0) or trans (TRA=1).
// ---------------------------------------------------------------------------
template<bool TRA>
__device__ __forceinline__ void gemm_avl(
    const __half* __restrict__ A, int lda,
    const __half* __restrict__ B, int ldb,
    __half* __restrict__ Ch, int ldc, int K, __half* hsm)
{
    constexpr int AT_H = TRA ? TTILE16 : TILE16;
    constexpr int STG  = AT_H + TTILE16;
    constexpr int NST  = 4;

    const int tid  = threadIdx.x;
    const int lane = tid & 31;
    const int wid  = tid >> 5;
    const int wm   = wid & 3;
    const int wn   = wid >> 2;
    const long m0  = (long)blockIdx.y * 128;
    const long n0  = (long)blockIdx.x * 128;
    const int lr   = lane >> 2;
    const int lc   = lane & 3;

    const uint32_t sb32 = smem_u32(hsm);
    const int loff   = (lane & 15) * ROWH + (lane >> 4) * 8;      // normal A
    const int rowsel = (lane & 7) + ((lane >> 4) << 3);           // trans tiles
    const int tcol   = lane & 8;

    float acc[2][8][4];
#pragma unroll
    for (int i = 0; i < 2; ++i)
#pragma unroll
        for (int j = 0; j < 8; ++j)
#pragma unroll
            for (int q = 0; q < 4; ++q) acc[i][j][q] = 0.f;

    const int NIT = K / 32;

    auto issue = [&](int st) {
        if (st < NIT) {
            __half* s = hsm + (st % NST) * STG;
            const int k0 = st * 32;
            if (!TRA) load_stage16(s, A, lda, m0, k0, tid);
            else      load_trans16(s, A, lda, m0, k0, tid);
            load_trans16(s + AT_H, B, ldb, n0, k0, tid);
        }
        CP_COMMIT();
    };

#pragma unroll
    for (int s = 0; s < NST - 1; ++s) issue(s);

    for (int it = 0; it < NIT; ++it) {
        cp_wait<NST - 2>();
        __syncthreads();
        issue(it + NST - 1);

        const int stA = (it % NST) * STG;
        const int stB = stA + AT_H;

#pragma unroll
        for (int ks = 0; ks < 2; ++ks) {
            const int kb = ks * 16;
            uint32_t ah[2][4];
#pragma unroll
            for (int mt = 0; mt < 2; ++mt) {
                if (!TRA) {
                    const int ao = (wm * 32 + mt * 16) * ROWH + loff + kb;
                    LDM4(ah[mt], sb32 + (uint32_t)(stA + ao) * 2);
                } else {
                    const int ao = (kb + rowsel) * TROW + wm * 32 + mt * 16 + tcol;
                    LDM4T(ah[mt], sb32 + (uint32_t)(stA + ao) * 2);
                }
            }
#pragma unroll
            for (int ntg = 0; ntg < 4; ++ntg) {
                const int bo = (kb + rowsel) * TROW + wn * 64 + ntg * 16 + tcol;
                uint32_t b4[4];
                LDM4T(b4, sb32 + (uint32_t)(stB + bo) * 2);
#pragma unroll
                for (int sub = 0; sub < 2; ++sub) {
                    uint32_t bb[2] = {b4[sub], b4[2 + sub]};
#pragma unroll
                    for (int mt = 0; mt < 2; ++mt)
                        mma16(acc[mt][ntg * 2 + sub], ah[mt], bb);
                }
            }
        }
    }

    // ---- epilogue (fp16 out) ----
#pragma unroll
    for (int mt = 0; mt < 2; ++mt) {
        const long r0 = m0 + wm * 32 + mt * 16 + lr;
#pragma unroll
        for (int nt = 0; nt < 8; ++nt) {
            const long c = n0 + wn * 64 + nt * 8 + lc * 2;
            *reinterpret_cast<__half2*>(&Ch[r0 * ldc + c]) =
                __floats2half2_rn(acc[mt][nt][0], acc[mt][nt][1]);
            *reinterpret_cast<__half2*>(&Ch[(r0 + 8) * ldc + c]) =
                __floats2half2_rn(acc[mt][nt][2], acc[mt][nt][3]);
        }
    }
}

// ---------------------------------------------------------------------------
// GEMM kernel wrappers (all 2 CTAs/SM)
// ---------------------------------------------------------------------------
__global__ __launch_bounds__(256, 2)
void proj_gemm(const __half* __restrict__ vfh, const __half* __restrict__ vfl,
               const __half* __restrict__ lfh, const __half* __restrict__ lfl,
               const __half* __restrict__ wvh, const __half* __restrict__ wvl,
               const __half* __restrict__ wlh, const __half* __restrict__ wll,
               const float* __restrict__ bv, const float* __restrict__ bl,
               __half* __restrict__ vph, __half* __restrict__ vpl,
               __half* __restrict__ lph, __half* __restrict__ lpl)
{
    extern __shared__ __half hsm[];
    const int z = blockIdx.z;
    gemm16_body<true, true, 2, 2, true>(
        z ? lfh : vfh, z ? lfl : vfl, DIM,
        z ? wlh : wvh, z ? wll : wvl, DIM,
        nullptr, z ? lph : vph, z ? lpl : vpl, DIM,
        DIM, z ? bl : bv, hsm);
}

__global__ __launch_bounds__(256, 2)
void sim_gemm(const __half* __restrict__ vph, const __half* __restrict__ vpl,
              const __half* __restrict__ lph, const __half* __restrict__ lpl,
              float* __restrict__ sim)
{
    extern __shared__ __half hsm[];
    const long b  = blockIdx.z;
    const long sF = (long)SEQ * DIM;
    const long sS = (long)SEQ * SEQ;
    gemm16_body<true, true, 2, 0, false>(
        vph + b * sF, vpl + b * sF, DIM,
        lph + b * sF, lpl + b * sF, DIM,
        sim + b * sS, nullptr, nullptr, SEQ, DIM, nullptr, hsm);
}

__global__ __launch_bounds__(256, 2)
void avl_gemm(const __half* __restrict__ at,
              const __half* __restrict__ vph, const __half* __restrict__ lph,
              __half* __restrict__ cb)
{
    extern __shared__ __half hsm[];
    const int z   = blockIdx.z;
    const long b  = z & 7;
    const long sS = (long)SEQ * SEQ;
    const long sF = (long)SEQ * DIM;
    const long sO = (long)SEQ * 2 * DIM;
    if ((z >> 3) == 0) {
        gemm_avl<false>(at + b * sS, SEQ, vph + b * sF, DIM,
                        cb + b * sO, 2 * DIM, SEQ, hsm);
    } else {
        gemm_avl<true>(at + b * sS, SEQ, lph + b * sF, DIM,
                       cb + b * sO + DIM, 2 * DIM, SEQ, hsm);
    }
}

__global__ __launch_bounds__(256, 2)
void out_gemm(const __half* __restrict__ cb,
              const __half* __restrict__ wo, const float* __restrict__ bo,
              float* __restrict__ out)
{
    extern __shared__ __half hsm[];
    gemm16_body<false, false, 3, 0, true>(
        cb, nullptr, 2 * DIM, wo, nullptr, 2 * DIM,
        out, nullptr, nullptr, DIM, 2 * DIM, bo, hsm);
}

// ---------------------------------------------------------------------------
// Fused conversion kernel: one launch covers all 5 inputs.
// Flat float4 index space:
//   [0, NV)            Vf   -> vfh/vfl split
//   [NV, 2NV)          Lf   -> lfh/lfl
//   [2NV, 2NV+NW)      Wv   -> wvh/wvl
//   [.., +NW)          Wl   -> wlh/wll
//   [.., +NO)          Wo   -> wo16 (single fp16)
// ---------------------------------------------------------------------------
#define NV4 (TOK * DIM / 4)        // 3145728
#define NW4 (DIM * DIM / 4)        // 147456
#define NO4 (DIM * 2 * DIM / 4)    // 294912
#define NCONV_TOTAL (2 * NV4 + 2 * NW4 + NO4)

__device__ __forceinline__ void split_store4(const float* src, __half* h, __half* l, long i)
{
    float4 v = reinterpret_cast<const float4*>(src)[i];
    __half hh[4], ll[4];
    split_h(v.x, hh[0], ll[0]); split_h(v.y, hh[1], ll[1]);
    split_h(v.z, hh[2], ll[2]); split_h(v.w, hh[3], ll[3]);
    uint2 ho, lo;
    *reinterpret_cast<__half2*>(&ho.x) = __halves2half2(hh[0], hh[1]);
    *reinterpret_cast<__half2*>(&ho.y) = __halves2half2(hh[2], hh[3]);
    *reinterpret_cast<__half2*>(&lo.x) = __halves2half2(ll[0], ll[1]);
    *reinterpret_cast<__half2*>(&lo.y) = __halves2half2(ll[2], ll[3]);
    reinterpret_cast<uint2*>(h)[i] = ho;
    reinterpret_cast<uint2*>(l)[i] = lo;
}

__global__ __launch_bounds__(256)
void convert_all(const float* __restrict__ Vf, const float* __restrict__ Lf,
                 const float* __restrict__ Wv, const float* __restrict__ Wl,
                 const float* __restrict__ Wo,
                 __half* __restrict__ vfh, __half* __restrict__ vfl,
                 __half* __restrict__ lfh, __half* __restrict__ lfl,
                 __half* __restrict__ wvh, __half* __restrict__ wvl,
                 __half* __restrict__ wlh, __half* __restrict__ wll,
                 __half* __restrict__ wo16)
{
    long i = (long)blockIdx.x * 256 + threadIdx.x;
    if (i < NV4) { split_store4(Vf, vfh, vfl, i); return; }
    i -= NV4;
    if (i < NV4) { split_store4(Lf, lfh, lfl, i); return; }
    i -= NV4;
    if (i < NW4) { split_store4(Wv, wvh, wvl, i); return; }
    i -= NW4;
    if (i < NW4) { split_store4(Wl, wlh, wll, i); return; }
    i -= NW4;
    {
        float4 v = reinterpret_cast<const float4*>(Wo)[i];
        uint2 o;
        *reinterpret_cast<__half2*>(&o.x) = __floats2half2_rn(v.x, v.y);
        *reinterpret_cast<__half2*>(&o.y) = __floats2half2_rn(v.z, v.w);
        reinterpret_cast<uint2*>(wo16)[i] = o;
    }
}

// ---------------------------------------------------------------------------
// Row softmax: sim fp32 -> attn fp16.  Streaming (read-once) loads for sim.
// ---------------------------------------------------------------------------
__global__ __launch_bounds__(256)
void softmax2048h(const float* __restrict__ S, __half* __restrict__ O)
{
    const float* p = S + (long)blockIdx.x * 2048;
    __half*      o = O + (long)blockIdx.x * 2048;
    const int tid = threadIdx.x;

    float4 v0 = ldcs4(reinterpret_cast<const float4*>(p) + tid);
    float4 v1 = ldcs4(reinterpret_cast<const float4*>(p) + tid + 256);

    float mx = fmaxf(fmaxf(fmaxf(v0.x, v0.y), fmaxf(v0.z, v0.w)),
                     fmaxf(fmaxf(v1.x, v1.y), fmaxf(v1.z, v1.w)));

    __shared__ float red[8];
#pragma unroll
    for (int ofs = 16; ofs > 0; ofs >>= 1) mx = fmaxf(mx, __shfl_xor_sync(0xffffffffu, mx, ofs));
    if ((tid & 31) == 0) red[tid >> 5] = mx;
    __syncthreads();
    if (tid == 0) {
        float m = red[0];
#pragma unroll
        for (int w = 1; w < 8; ++w) m = fmaxf(m, red[w]);
        red[0] = m;
    }
    __syncthreads();
    mx = red[0];
    __syncthreads();

    v0.x = __expf(v0.x - mx); v0.y = __expf(v0.y - mx);
    v0.z = __expf(v0.z - mx); v0.w = __expf(v0.w - mx);
    v1.x = __expf(v1.x - mx); v1.y = __expf(v1.y - mx);
    v1.z = __expf(v1.z - mx); v1.w = __expf(v1.w - mx);

    float s = (v0.x + v0.y + v0.z + v0.w) + (v1.x + v1.y + v1.z + v1.w);
#pragma unroll
    for (int ofs = 16; ofs > 0; ofs >>= 1) s += __shfl_xor_sync(0xffffffffu, s, ofs);
    if ((tid & 31) == 0) red[tid >> 5] = s;
    __syncthreads();
    if (tid == 0) {
        float t = 0.f;
#pragma unroll
        for (int w = 0; w < 8; ++w) t += red[w];
        red[0] = t;
    }
    __syncthreads();
    const float inv = 1.0f / red[0];

    uint2 o0, o1;
    *reinterpret_cast<__half2*>(&o0.x) = __floats2half2_rn(v0.x * inv, v0.y * inv);
    *reinterpret_cast<__half2*>(&o0.y) = __floats2half2_rn(v0.z * inv, v0.w * inv);
    *reinterpret_cast<__half2*>(&o1.x) = __floats2half2_rn(v1.x * inv, v1.y * inv);
    *reinterpret_cast<__half2*>(&o1.y) = __floats2half2_rn(v1.z * inv, v1.w * inv);
    reinterpret_cast<uint2*>(o)[tid]       = o0;
    reinterpret_cast<uint2*>(o)[tid + 256] = o1;
}

// ---------------------------------------------------------------------------
// Launch
// ---------------------------------------------------------------------------
extern "C" void kernel_launch(void* const* d_in, const int* in_sizes, int n_in,
                              void* d_out, int out_size)
{
    const float* Vf = (const float*)d_in[0];
    const float* Lf = (const float*)d_in[1];
    const float* Wv = (const float*)d_in[2];
    const float* bv = (const float*)d_in[3];
    const float* Wl = (const float*)d_in[4];
    const float* bl = (const float*)d_in[5];
    const float* Wo = (const float*)d_in[6];
    const float* bo = (const float*)d_in[7];
    float* out = (float*)d_out;

    __half *vfh, *vfl, *lfh, *lfl, *wvh, *wvl, *wlh, *wll;
    __half *vph, *vpl, *lph, *lpl, *at, *cb, *wo16;
    float* sim;
    cudaGetSymbolAddress((void**)&vfh, g_vfh);
    cudaGetSymbolAddress((void**)&vfl, g_vfl);
    cudaGetSymbolAddress((void**)&lfh, g_lfh);
    cudaGetSymbolAddress((void**)&lfl, g_lfl);
    cudaGetSymbolAddress((void**)&wvh, g_wvh);
    cudaGetSymbolAddress((void**)&wvl, g_wvl);
    cudaGetSymbolAddress((void**)&wlh, g_wlh);
    cudaGetSymbolAddress((void**)&wll, g_wll);
    cudaGetSymbolAddress((void**)&vph, g_vph);
    cudaGetSymbolAddress((void**)&vpl, g_vpl);
    cudaGetSymbolAddress((void**)&lph, g_lph);
    cudaGetSymbolAddress((void**)&lpl, g_lpl);
    cudaGetSymbolAddress((void**)&sim, g_sim);
    cudaGetSymbolAddress((void**)&at,  g_at);
    cudaGetSymbolAddress((void**)&cb,  g_cb);
    cudaGetSymbolAddress((void**)&wo16, g_wo16);

    const int S2  = 4 * TILE16 * 2 * 2;                 // 81920 (proj, sim)
    const int SAV = 4 * (TILE16 + TTILE16) * 2;         // 75776 (avl, worst mode)
    const int S3  = 2 * TILE16 * 3 * 2;                 // 61440 (out)
    cudaFuncSetAttribute(proj_gemm, cudaFuncAttributeMaxDynamicSharedMemorySize, S2);
    cudaFuncSetAttribute(sim_gemm,  cudaFuncAttributeMaxDynamicSharedMemorySize, S2);
    cudaFuncSetAttribute(avl_gemm,  cudaFuncAttributeMaxDynamicSharedMemorySize, SAV);
    cudaFuncSetAttribute(out_gemm,  cudaFuncAttributeMaxDynamicSharedMemorySize, S3);

    const dim3 blk(256);

    // all input conversions, one launch
    convert_all<<<NCONV_TOTAL / 256, blk>>>(
        Vf, Lf, Wv, Wl, Wo,
        vfh, vfl, lfh, lfl, wvh, wvl, wlh, wll, wo16);
    // projections (3x) -> vp/lp hi+lo fp16
    proj_gemm<<<dim3(DIM/128, TOK/128, 2), blk, S2>>>(
        vfh, vfl, lfh, lfl, wvh, wvl, wlh, wll, bv, bl, vph, vpl, lph, lpl);
    // sim (3x)
    sim_gemm<<<dim3(SEQ/128, SEQ/128, BATCH), blk, S2>>>(vph, vpl, lph, lpl, sim);
    // softmax -> attn fp16
    softmax2048h<<<TOK, blk>>>(sim, at);
    // av + al (1x) -> comb fp16, transposes folded into ldmatrix.trans
    avl_gemm<<<dim3(DIM/128, SEQ/128, 2 * BATCH), blk, SAV>>>(at, vph, lph, cb);
    // out (1x)
    out_gemm<<<dim3(DIM/128, TOK/128, 1), blk, S3>>>(cb, wo16, bo, out);
}